// round 13
// baseline (speedup 1.0000x reference)
#include <cuda_runtime.h>
#include <math.h>

constexpr int Tt  = 2048;
constexpr int DHd = 512;
constexpr int NT  = 8 * 2048;
constexpr float SCALE = 0.044194173824159216f; // 512^-0.5

__device__ float g_q [NT * DHd];
__device__ float g_k [NT * DHd];
__device__ float g_v [NT * DHd];
__device__ float g_g [NT * DHd];
__device__ float g_Qc[NT * DHd];
__device__ float g_Qr[NT * DHd];
__device__ float g_Kr[NT * DHd];
__device__ float g_Qg[NT * DHd];
__device__ float g_Kg[NT * DHd];
__device__ float g_M [DHd * DHd];
__device__ float g_hist[8 * 32 * DHd];
__device__ float g_cos[Tt * 256];
__device__ float g_sin[Tt * 256];

// ---------------- GEMM (unchanged, ~88% of fp32 FFMA ceiling) ----------------
template<int MODE, int TRANSB, int SEL>
__global__ void gemm64(const float* __restrict__ Ain,
                       const float* __restrict__ Bin,
                       const float* __restrict__ bias) {
    const float* A;
    float* C;
    if constexpr (SEL == 0)      { A = Ain;  C = g_q;  }
    else if constexpr (SEL == 1) { A = Ain;  C = g_k;  }
    else if constexpr (SEL == 2) { A = Ain;  C = g_v;  }
    else if constexpr (SEL == 3) { A = Ain;  C = g_g;  }
    else if constexpr (SEL == 4) { A = g_Qr; C = g_Qg; }
    else                         { A = g_Kr; C = g_Kg; }
    const float* Bm = (SEL >= 4) ? (const float*)g_M : Bin;

    constexpr int K = 512, N = 512;
    __shared__ float As[16][68];
    __shared__ float Bs[16][68];
    const int t  = threadIdx.x;
    const int tx = t & 15, ty = t >> 4;
    const int n0 = blockIdx.x * 64, m0 = blockIdx.y * 64;
    const int ar = t >> 2, ac = (t & 3) << 2;
    float acc[4][4] = {};

    for (int k0 = 0; k0 < K; k0 += 16) {
        float4 va = *(const float4*)&A[(size_t)(m0 + ar) * K + k0 + ac];
        As[ac + 0][ar] = va.x; As[ac + 1][ar] = va.y;
        As[ac + 2][ar] = va.z; As[ac + 3][ar] = va.w;
        if constexpr (TRANSB) {
            float4 vb = *(const float4*)&Bm[(size_t)(n0 + ar) * K + k0 + ac];
            Bs[ac + 0][ar] = vb.x; Bs[ac + 1][ar] = vb.y;
            Bs[ac + 2][ar] = vb.z; Bs[ac + 3][ar] = vb.w;
        } else {
            *(float4*)&Bs[ty][tx << 2] =
                *(const float4*)&Bm[(size_t)(k0 + ty) * N + n0 + (tx << 2)];
        }
        __syncthreads();
        #pragma unroll
        for (int kk = 0; kk < 16; kk++) {
            float4 a4 = *(const float4*)&As[kk][ty << 2];
            float4 b4 = *(const float4*)&Bs[kk][tx << 2];
            float av[4] = {a4.x, a4.y, a4.z, a4.w};
            float bv[4] = {b4.x, b4.y, b4.z, b4.w};
            #pragma unroll
            for (int i = 0; i < 4; i++)
                #pragma unroll
                for (int j = 0; j < 4; j++)
                    acc[i][j] += av[i] * bv[j];
        }
        __syncthreads();
    }
    #pragma unroll
    for (int i = 0; i < 4; i++) {
        size_t rowb = (size_t)(m0 + (ty << 2) + i) * N;
        #pragma unroll
        for (int j = 0; j < 4; j++) {
            int n = n0 + (tx << 2) + j;
            float v = acc[i][j];
            if constexpr (MODE == 1) v = 1.f / (1.f + __expf(-(v + bias[n])));
            C[rowb + n] = v;
        }
    }
}

__global__ void rope_table() {
    int tp = blockIdx.x, p = threadIdx.x;
    double invf = pow(10000.0, -((double)(2 * p)) / 512.0);
    float ang = (float)tp * (float)invf;
    g_cos[tp * 256 + p] = (float)cos((double)ang);
    g_sin[tp * 256 + p] = (float)sin((double)ang);
}

__global__ void build_M(const float* __restrict__ A) {
    int idx = blockIdx.x * 256 + threadIdx.x;
    int d = idx >> 9, e = idx & 511;
    g_M[idx] = ((d == e) ? 1.f : 0.f) + A[idx] - A[(size_t)e * 512 + d];
}

// ---------------- Fused recurrence step: scores+softmax, then
// retrieval+cumsum+hist. grid=8 (batch), 512 threads. ----------------
__global__ __launch_bounds__(512)
void chunk_step(int i) {
    const int b = blockIdx.x;
    __shared__ float sw[64][36];
    const int t = threadIdx.x;

    for (int idx = t; idx < 64 * 36; idx += 512) ((float*)sw)[idx] = 0.f;
    __syncthreads();

    if (i > 0) {
        const int w = t >> 5, lane = t & 31;
        const float* hb = g_hist + (size_t)b * 32 * 512;
        #pragma unroll
        for (int rr = 0; rr < 4; rr++) {
            const int c = (w << 2) | rr;
            const float* krow = g_k + ((size_t)(b * 2048 + (i << 6) + c)) * 512;
            for (int j = 0; j < i; j += 2) {
                bool has1 = (j + 1 < i);
                const float* h0 = hb + ((size_t)j << 9);
                const float* h1 = hb + ((size_t)(j + 1) << 9);
                float a0 = 0.f, a1 = 0.f;
                for (int d = lane << 2; d < 512; d += 128) {
                    float4 kv = *(const float4*)&krow[d];
                    float4 v0 = *(const float4*)&h0[d];
                    a0 += kv.x * v0.x + kv.y * v0.y + kv.z * v0.z + kv.w * v0.w;
                    if (has1) {
                        float4 v1 = *(const float4*)&h1[d];
                        a1 += kv.x * v1.x + kv.y * v1.y + kv.z * v1.z + kv.w * v1.w;
                    }
                }
                #pragma unroll
                for (int o = 16; o > 0; o >>= 1) {
                    a0 += __shfl_xor_sync(0xffffffffu, a0, o);
                    a1 += __shfl_xor_sync(0xffffffffu, a1, o);
                }
                if (lane == 0) {
                    sw[c][j] = a0 * SCALE;
                    if (has1) sw[c][j + 1] = a1 * SCALE;
                }
            }
        }
        __syncwarp();
        #pragma unroll
        for (int rr = 0; rr < 4; rr++) {
            const int c = (w << 2) | rr;
            float v = (lane < i) ? sw[c][lane] : -1e30f;
            float mx = v;
            #pragma unroll
            for (int o = 16; o > 0; o >>= 1)
                mx = fmaxf(mx, __shfl_xor_sync(0xffffffffu, mx, o));
            float e = (lane < i) ? __expf(v - mx) : 0.f;
            float s = e;
            #pragma unroll
            for (int o = 16; o > 0; o >>= 1)
                s += __shfl_xor_sync(0xffffffffu, s, o);
            sw[c][lane] = (lane < i) ? (e / s) : 0.f;
        }
    }
    __syncthreads();

    // phase B: one d column per thread
    const int d = t;
    float hv[32];
    #pragma unroll
    for (int j = 0; j < 32; j++)
        hv[j] = (j < i) ? g_hist[((size_t)(b * 32 + j) << 9) + d] : 0.f;
    const float base = (i > 0) ? g_hist[((size_t)(b * 32 + i - 1) << 9) + d] : 0.f;
    const size_t rb = ((size_t)(b * 2048 + (i << 6)) << 9) + d;
    float run = 0.f, val = 0.f;
    #pragma unroll
    for (int ch = 0; ch < 2; ch++) {
        float qi_[32];
        #pragma unroll
        for (int cc = 0; cc < 32; cc++) {
            int c = (ch << 5) + cc;
            float s = 0.f;
            #pragma unroll
            for (int jq = 0; jq < 8; jq++) {
                float4 wv = *(const float4*)&sw[c][jq << 2];
                s += wv.x * hv[4 * jq] + wv.y * hv[4 * jq + 1]
                   + wv.z * hv[4 * jq + 2] + wv.w * hv[4 * jq + 3];
            }
            qi_[cc] = s;
        }
        #pragma unroll
        for (int cc = 0; cc < 32; cc++) {
            int c = (ch << 5) + cc;
            size_t idx = rb + ((size_t)c << 9);
            run += g_g[idx] * g_q[idx];
            val = run + ((i > 0) ? (base + qi_[cc]) : 0.f);
            g_Qc[idx] = val;
        }
    }
    g_hist[((size_t)(b * 32 + i) << 9) + d] = val;
}

// ---------------- norm + rope (unchanged) ----------------
__global__ void norm_rope() {
    const size_t row = blockIdx.x;
    const int tpos = (int)(row & 2047);
    const float* qc = g_Qc + row * 512;
    const float* kr = g_k + row * 512;
    __shared__ float red[8][4];
    __shared__ float stats[2];
    const int t = threadIdx.x;
    const int w = t >> 5, lane = t & 31;

    float a0 = qc[t], a1 = qc[t + 256];
    float c0 = kr[t], c1 = kr[t + 256];
    float sq = a0 + a1, sq2 = a0 * a0 + a1 * a1;
    float sk = c0 + c1, sk2 = c0 * c0 + c1 * c1;
    #pragma unroll
    for (int o = 16; o > 0; o >>= 1) {
        sq  += __shfl_xor_sync(0xffffffffu, sq,  o);
        sq2 += __shfl_xor_sync(0xffffffffu, sq2, o);
        sk  += __shfl_xor_sync(0xffffffffu, sk,  o);
        sk2 += __shfl_xor_sync(0xffffffffu, sk2, o);
    }
    if (lane == 0) { red[w][0] = sq; red[w][1] = sq2; red[w][2] = sk; red[w][3] = sk2; }
    __syncthreads();
    if (t == 0) {
        float A = 0, B2 = 0, C3 = 0, D4 = 0;
        #pragma unroll
        for (int ww = 0; ww < 8; ww++) {
            A += red[ww][0]; B2 += red[ww][1]; C3 += red[ww][2]; D4 += red[ww][3];
        }
        float mq = A / 512.f, mk = C3 / 512.f;
        float vq = (B2 - 512.f * mq * mq) / 511.f;
        float vk = (D4 - 512.f * mk * mk) / 511.f;
        float std_s = 0.5f * (sqrtf(fmaxf(vq, 0.f)) + sqrtf(fmaxf(vk, 0.f)));
        stats[0] = 0.5f * (mq + mk);
        stats[1] = 1.f / (std_s + 1e-6f);
    }
    __syncthreads();
    const float mean = stats[0], inv = stats[1];
    const float cs = g_cos[tpos * 256 + t];
    const float sn = g_sin[tpos * 256 + t];
    float q1 = (qc[2 * t]     - mean) * inv;
    float q2 = (qc[2 * t + 1] - mean) * inv;
    float k1 = (kr[2 * t]     - mean) * inv;
    float k2 = (kr[2 * t + 1] - mean) * inv;
    g_Qr[row * 512 + t]       = q1 * cs - q2 * sn;
    g_Qr[row * 512 + t + 256] = q1 * sn + q2 * cs;
    g_Kr[row * 512 + t]       = k1 * cs - k2 * sn;
    g_Kr[row * 512 + t + 256] = k1 * sn + k2 * cs;
}

// ---------------- Flash attention: Bq=64, Bk=128 panels, 8x4 microtile,
// 256 threads, 64x512 fp32 accumulator in shared. ----------------
constexpr int FA_STR = 516;
constexpr int OFF_ST = 64 * FA_STR;              // S^T [128][68]
constexpr int OFF_X  = OFF_ST + 128 * 68;
constexpr int OFF_QT = OFF_X;                    // Q^T [64][68]
constexpr int OFF_KT = OFF_X + 64 * 68;          // K^T [64][132]
constexpr int OFF_V  = OFF_X;                    // V   [64][132] (PV phase)
constexpr int OFF_M  = OFF_X + 64 * 68 + 64 * 132;
constexpr int OFF_L  = OFF_M + 64;
constexpr int OFF_AL = OFF_L + 64;
constexpr int FTOTAL = OFF_AL + 64;              // 54720 floats = 218880 B

__global__ __launch_bounds__(256)
void flash_kernel(const float* __restrict__ sinkp,
                  const float* __restrict__ vnull,
                  float* __restrict__ out) {
    extern __shared__ float sh[];
    float* sAcc = sh;
    float* sSt  = sh + OFF_ST;
    float* sQt  = sh + OFF_QT;
    float* sKt  = sh + OFF_KT;
    float* sV   = sh + OFF_V;
    float* sM   = sh + OFF_M;
    float* sL   = sh + OFF_L;
    float* sAl  = sh + OFF_AL;

    const int t  = threadIdx.x;
    const int qi = 31 - (blockIdx.x >> 3);       // heavy tiles first
    const int b  = blockIdx.x & 7;
    const int q0 = qi << 6;
    const size_t bT = (size_t)b * 2048;
    const int tq = t >> 5;                        // 0..7 (warp-uniform)
    const int tk = t & 31;                        // 0..31
    const int kr2 = t >> 1, kk2 = (t & 1) << 2;   // K staging
    const int qr4 = t >> 2, qk4 = (t & 3) << 2;   // Q staging

    for (int f4 = t; f4 < (64 * FA_STR) / 4; f4 += 256)
        ((float4*)sAcc)[f4] = make_float4(0.f, 0.f, 0.f, 0.f);
    if (t < 64) { sM[t] = -1e30f; sL[t] = 0.f; }
    __syncthreads();

    const int npair = (qi >> 1) + 1;
    for (int pp = 0; pp < npair; pp++) {
        const int k0 = pp << 7;
        const bool last = (pp == npair - 1);
        float sc[8][4] = {};

        // ---- S = Q K^T over d chunks of 64 (transposed staging) ----
        for (int dc = 0; dc < 512; dc += 64) {
            #pragma unroll
            for (int m = 0; m < 4; m++) {
                int dd = qk4 + (m << 4);
                float4 qv = *(const float4*)&g_Qg[(bT + q0 + qr4) * 512 + dc + dd];
                sQt[(dd + 0) * 68 + qr4] = qv.x;
                sQt[(dd + 1) * 68 + qr4] = qv.y;
                sQt[(dd + 2) * 68 + qr4] = qv.z;
                sQt[(dd + 3) * 68 + qr4] = qv.w;
            }
            #pragma unroll
            for (int m = 0; m < 8; m++) {
                int dd = kk2 + (m << 3);
                float4 kv = *(const float4*)&g_Kg[(bT + k0 + kr2) * 512 + dc + dd];
                sKt[(dd + 0) * 132 + kr2] = kv.x;
                sKt[(dd + 1) * 132 + kr2] = kv.y;
                sKt[(dd + 2) * 132 + kr2] = kv.z;
                sKt[(dd + 3) * 132 + kr2] = kv.w;
            }
            __syncthreads();
            #pragma unroll 8
            for (int dd = 0; dd < 64; dd++) {
                float4 a0 = *(const float4*)&sQt[dd * 68 + (tq << 3)];
                float4 a1 = *(const float4*)&sQt[dd * 68 + (tq << 3) + 4];
                float4 b4 = *(const float4*)&sKt[dd * 132 + (tk << 2)];
                float av[8] = {a0.x, a0.y, a0.z, a0.w, a1.x, a1.y, a1.z, a1.w};
                float bv[4] = {b4.x, b4.y, b4.z, b4.w};
                #pragma unroll
                for (int i = 0; i < 8; i++)
                    #pragma unroll
                    for (int j = 0; j < 4; j++)
                        sc[i][j] += av[i] * bv[j];
            }
            __syncthreads();
        }
        // ---- write S^T with scale + causal mask ----
        #pragma unroll
        for (int j = 0; j < 4; j++) {
            const int c = (tk << 2) + j;
            float s8[8];
            #pragma unroll
            for (int i = 0; i < 8; i++) {
                int r = (tq << 3) + i;
                float s = sc[i][j] * SCALE;
                if (last && (k0 + c > q0 + r)) s = -1e30f;
                s8[i] = s;
            }
            *(float4*)&sSt[c * 68 + (tq << 3)]     = make_float4(s8[0], s8[1], s8[2], s8[3]);
            *(float4*)&sSt[c * 68 + (tq << 3) + 4] = make_float4(s8[4], s8[5], s8[6], s8[7]);
        }
        __syncthreads();
        // ---- online softmax: 4 threads per row over 128 cols ----
        {
            const int r = t >> 2, sub = t & 3;
            float mx = -1e30f;
            for (int c = sub; c < 128; c += 4) mx = fmaxf(mx, sSt[c * 68 + r]);
            mx = fmaxf(mx, __shfl_xor_sync(0xffffffffu, mx, 1));
            mx = fmaxf(mx, __shfl_xor_sync(0xffffffffu, mx, 2));
            float mold = sM[r];
            float mnew = fmaxf(mold, mx);
            float ls = 0.f;
            for (int c = sub; c < 128; c += 4) {
                float e = __expf(sSt[c * 68 + r] - mnew);
                sSt[c * 68 + r] = e;
                ls += e;
            }
            ls += __shfl_xor_sync(0xffffffffu, ls, 1);
            ls += __shfl_xor_sync(0xffffffffu, ls, 2);
            if (sub == 0) {
                float al = __expf(mold - mnew);
                sAl[r] = al;
                sM[r] = mnew;
                sL[r] = sL[r] * al + ls;
            }
        }
        __syncthreads();
        // ---- O = al*O + P V : d-chunks of 128, s-subpanels of 64 ----
        for (int dcb = 0; dcb < 512; dcb += 128) {
            float o[8][4] = {};
            #pragma unroll
            for (int shh = 0; shh < 2; shh++) {
                for (int f4 = t; f4 < 64 * 32; f4 += 256) {
                    int row = f4 >> 5, c4 = (f4 & 31) << 2;
                    *(float4*)&sV[row * 132 + c4] =
                        *(const float4*)&g_v[(bT + k0 + (shh << 6) + row) * 512 + dcb + c4];
                }
                __syncthreads();
                #pragma unroll 8
                for (int s = 0; s < 64; s++) {
                    const int sg = (shh << 6) + s;
                    float4 p0 = *(const float4*)&sSt[sg * 68 + (tq << 3)];
                    float4 p1 = *(const float4*)&sSt[sg * 68 + (tq << 3) + 4];
                    float4 v4 = *(const float4*)&sV[s * 132 + (tk << 2)];
                    float pv[8] = {p0.x, p0.y, p0.z, p0.w, p1.x, p1.y, p1.z, p1.w};
                    float vv[4] = {v4.x, v4.y, v4.z, v4.w};
                    #pragma unroll
                    for (int i = 0; i < 8; i++)
                        #pragma unroll
                        for (int j = 0; j < 4; j++)
                            o[i][j] += pv[i] * vv[j];
                }
                __syncthreads();
            }
            #pragma unroll
            for (int i = 0; i < 8; i++) {
                const int r = (tq << 3) + i;
                const float al = sAl[r];
                float4* ap = (float4*)&sAcc[r * FA_STR + dcb + (tk << 2)];
                float4 a = *ap;
                a.x = a.x * al + o[i][0];
                a.y = a.y * al + o[i][1];
                a.z = a.z * al + o[i][2];
                a.w = a.w * al + o[i][3];
                *ap = a;
            }
        }
        __syncthreads();
    }
    // ---- epilogue: fold sink, normalize, write ----
    {
        const float skv = *sinkp;
        const int r = t >> 2, sub = t & 3;
        const float m = sM[r], l = sL[r];
        const float M2 = fmaxf(m, skv);
        const float em = __expf(m - M2);
        const float es = __expf(skv - M2);
        const float inv = 1.f / (l * em + es);
        const size_t ob = (bT + q0 + r) * (size_t)512;
        for (int d = sub * 128; d < sub * 128 + 128; d += 4) {
            float4 a = *(float4*)&sAcc[r * FA_STR + d];
            float4 vn = *(const float4*)&vnull[d];
            float4 o;
            o.x = (a.x * em + es * vn.x) * inv;
            o.y = (a.y * em + es * vn.y) * inv;
            o.z = (a.z * em + es * vn.z) * inv;
            o.w = (a.w * em + es * vn.w) * inv;
            *(float4*)&out[ob + d] = o;
        }
    }
}

// ---------------- launch ----------------
extern "C" void kernel_launch(void* const* d_in, const int* in_sizes, int n_in,
                              void* d_out, int out_size) {
    const float* x     = (const float*)d_in[0];
    const float* Wq    = (const float*)d_in[1];
    const float* Wk    = (const float*)d_in[2];
    const float* Wv    = (const float*)d_in[3];
    const float* Wg    = (const float*)d_in[4];
    const float* bg    = (const float*)d_in[5];
    const float* A     = (const float*)d_in[6];
    const float* sink  = (const float*)d_in[7];
    const float* vnull = (const float*)d_in[8];
    float* out = (float*)d_out;

    cudaFuncSetAttribute(flash_kernel,
                         cudaFuncAttributeMaxDynamicSharedMemorySize,
                         FTOTAL * (int)sizeof(float));

    dim3 gg(8, 256);
    gemm64<0, 1, 0><<<gg, 256>>>(x, Wq, nullptr);
    gemm64<0, 1, 1><<<gg, 256>>>(x, Wk, nullptr);
    gemm64<0, 1, 2><<<gg, 256>>>(x, Wv, nullptr);
    gemm64<1, 1, 3><<<gg, 256>>>(x, Wg, bg);

    rope_table<<<2048, 256>>>();
    build_M<<<1024, 256>>>(A);

    for (int i = 0; i < 32; i++)
        chunk_step<<<8, 512>>>(i);

    norm_rope<<<16384, 256>>>();

    gemm64<0, 0, 4><<<gg, 256>>>(nullptr, nullptr, nullptr);  // Qg = Qr @ M
    gemm64<0, 0, 5><<<gg, 256>>>(nullptr, nullptr, nullptr);  // Kg = Kr @ M

    flash_kernel<<<256, 256, FTOTAL * (int)sizeof(float)>>>(sink, vnull, out);
}